// round 14
// baseline (speedup 1.0000x reference)
#include <cuda_runtime.h>
#include <math.h>

#define HX_B 16
#define HX_C 256
#define HX_H 128
#define HX_W 128
#define HX_HW (HX_H * HX_W)      // 16384
#define HX_HW4 (HX_HW / 4)       // 4096

#define CH_B 2                   // batches per chunk (32 MiB of x)
#define NCHUNK (HX_B / CH_B)     // 8 chunks

// reduce: block = 16 ch-slices x 16 pixel-quads, 16 channels/thread
#define RED_SLICES 16
#define RED_CPT (HX_C / RED_SLICES)             // 16
#define RED_PIX 16
#define NRED_BLOCKS (CH_B * HX_HW4 / RED_PIX)   // 512

// apply: block = 32 ch-slices x 8 pixel-quads, 8 channels/thread
#define APP_SLICES 32
#define APP_CPT (HX_C / APP_SLICES)             // 8
#define APP_PIX 8
#define NAPP_BLOCKS (CH_B * HX_HW4 / APP_PIX)   // 1024

// scratch (device globals: allocation-free per harness rules)
__device__ float g_avg[HX_B * HX_HW];   // 1 MiB
__device__ float g_max[HX_B * HX_HW];   // 1 MiB

// ---------------------------------------------------------------------------
// Reduce (per chunk): mean & max over C=256. Default cache policy — x(k)
// must linger in L2 for apply(k) running concurrently in the other stream.
// ---------------------------------------------------------------------------
__global__ void __launch_bounds__(256, 8) reduce_kernel(const float4* __restrict__ x4,
                                                        int b0) {
    __shared__ float4 s_sum[RED_SLICES * RED_PIX];
    __shared__ float4 s_max[RED_SLICES * RED_PIX];

    int tid   = threadIdx.x;
    int pix   = tid & (RED_PIX - 1);        // 0..15
    int slice = tid >> 4;                   // 0..15
    int lpix  = blockIdx.x * RED_PIX + pix; // 0..CH_B*HW4-1
    int b     = b0 + (lpix >> 12);          // /4096
    int hw4   = lpix & (HX_HW4 - 1);

    const float4* p = x4 + (size_t)b * HX_C * HX_HW4
                         + (size_t)(slice * RED_CPT) * HX_HW4 + hw4;

    float sx = 0.f, sy = 0.f, sz = 0.f, sw = 0.f;
    float mx = -INFINITY, my = -INFINITY, mz = -INFINITY, mw = -INFINITY;
    #pragma unroll
    for (int c = 0; c < RED_CPT; c++) {
        float4 v = p[(size_t)c * HX_HW4];
        sx += v.x; sy += v.y; sz += v.z; sw += v.w;
        mx = fmaxf(mx, v.x); my = fmaxf(my, v.y);
        mz = fmaxf(mz, v.z); mw = fmaxf(mw, v.w);
    }
    s_sum[tid] = make_float4(sx, sy, sz, sw);
    s_max[tid] = make_float4(mx, my, mz, mw);
    __syncthreads();

    if (tid < RED_PIX) {
        float4 a = s_sum[tid];
        #pragma unroll
        for (int k = 1; k < RED_SLICES; k++) {
            float4 a2 = s_sum[k * RED_PIX + tid];
            a.x += a2.x; a.y += a2.y; a.z += a2.z; a.w += a2.w;
        }
        const float inv = 1.0f / HX_C;
        a.x *= inv; a.y *= inv; a.z *= inv; a.w *= inv;
        int lp = blockIdx.x * RED_PIX + tid;
        int gp = (b0 + (lp >> 12)) * HX_HW4 + (lp & (HX_HW4 - 1));
        reinterpret_cast<float4*>(g_avg)[gp] = a;
    } else if (tid < 2 * RED_PIX) {
        int q = tid - RED_PIX;
        float4 m = s_max[q];
        #pragma unroll
        for (int k = 1; k < RED_SLICES; k++) {
            float4 m2 = s_max[k * RED_PIX + q];
            m.x = fmaxf(m.x, m2.x); m.y = fmaxf(m.y, m2.y);
            m.z = fmaxf(m.z, m2.z); m.w = fmaxf(m.w, m2.w);
        }
        int lp = blockIdx.x * RED_PIX + q;
        int gp = (b0 + (lp >> 12)) * HX_HW4 + (lp & (HX_HW4 - 1));
        reinterpret_cast<float4*>(g_max)[gp] = m;
    }
}

// ---------------------------------------------------------------------------
// Apply (per chunk): warp 0 computes the 32 sub-pixel stencil+sigmoid
// factors; then 256 threads stream 8 channels each as two batches of 4
// front-loaded float4s (MLP=4). __ldcs/__stcs: dead-after-use lines.
// ---------------------------------------------------------------------------
__device__ __forceinline__ float ld_plane(const float* __restrict__ y,
                                          int h, int w) {
    return (h >= 0 && h < HX_H && w >= 0 && w < HX_W) ? __ldg(y + h * HX_W + w)
                                                      : 0.f;
}

__global__ void __launch_bounds__(256, 6) apply_kernel(const float4* __restrict__ x4,
                                                       float4* __restrict__ o4,
                                                       const float* __restrict__ wts,
                                                       int b0) {
    __shared__ __align__(16) float s_fac[APP_PIX * 4];   // 32 sub-pixel factors

    int tid   = threadIdx.x;
    int pix   = tid & (APP_PIX - 1);        // 0..7
    int slice = tid >> 3;                   // 0..31
    int lpix  = blockIdx.x * APP_PIX + pix;
    int b     = b0 + (lpix >> 12);
    int hw4   = lpix & (HX_HW4 - 1);

    if (tid < 32) {                         // warp 0: one sub-pixel per lane
        int q   = tid >> 2;                 // quad 0..7
        int sub = tid & 3;
        int lq  = blockIdx.x * APP_PIX + q;
        int bq  = b0 + (lq >> 12);
        int hq4 = lq & (HX_HW4 - 1);
        int h   = hq4 >> 5;
        int w   = (hq4 & 31) * 4 + sub;
        float acc = 0.f;
        #pragma unroll
        for (int m = 0; m < 2; m++) {
            const float* y = (m == 0 ? g_avg : g_max) + bq * HX_HW;
            float p0 = __ldg(wts + bq * 8 + m * 4 + 0);
            float p1 = __ldg(wts + bq * 8 + m * 4 + 1);
            float p2 = __ldg(wts + bq * 8 + m * 4 + 2);
            float p3 = __ldg(wts + bq * 8 + m * 4 + 3);
            float pc = -(p0 + p1 + p2 + p3);
            acc += p0 * ld_plane(y, h - 1, w)
                 + p1 * ld_plane(y, h + 1, w)
                 + p2 * ld_plane(y, h, w - 1)
                 + p3 * ld_plane(y, h, w + 1)
                 + pc * ld_plane(y, h, w);
        }
        s_fac[tid] = 1.0f + 1.0f / (1.0f + __expf(-acc));
    }
    __syncthreads();
    float4 f = reinterpret_cast<const float4*>(s_fac)[pix];

    size_t base = (size_t)b * HX_C * HX_HW4
                + (size_t)(slice * APP_CPT) * HX_HW4 + hw4;
    const float4* px = x4 + base;
    float4*       po = o4 + base;

    #pragma unroll
    for (int batch = 0; batch < APP_CPT / 4; batch++) {
        float4 v0 = __ldcs(px + (size_t)(batch * 4 + 0) * HX_HW4);
        float4 v1 = __ldcs(px + (size_t)(batch * 4 + 1) * HX_HW4);
        float4 v2 = __ldcs(px + (size_t)(batch * 4 + 2) * HX_HW4);
        float4 v3 = __ldcs(px + (size_t)(batch * 4 + 3) * HX_HW4);
        v0.x *= f.x; v0.y *= f.y; v0.z *= f.z; v0.w *= f.w;
        v1.x *= f.x; v1.y *= f.y; v1.z *= f.z; v1.w *= f.w;
        v2.x *= f.x; v2.y *= f.y; v2.z *= f.z; v2.w *= f.w;
        v3.x *= f.x; v3.y *= f.y; v3.z *= f.z; v3.w *= f.w;
        __stcs(po + (size_t)(batch * 4 + 0) * HX_HW4, v0);
        __stcs(po + (size_t)(batch * 4 + 1) * HX_HW4, v1);
        __stcs(po + (size_t)(batch * 4 + 2) * HX_HW4, v2);
        __stcs(po + (size_t)(batch * 4 + 3) * HX_HW4, v3);
    }
}

// ---------------------------------------------------------------------------
// Launch: stream R runs reduces back-to-back; stream A runs applies, each
// gated on its chunk's reduce via event. reduce(k+1) overlaps apply(k).
// Streams/events created once on the first (eager, pre-capture) call; the
// event fork/join pattern is graph-capture legal and becomes graph edges.
// ---------------------------------------------------------------------------
extern "C" void kernel_launch(void* const* d_in, const int* in_sizes, int n_in,
                              void* d_out, int out_size) {
    const float4* x4  = (const float4*)d_in[0];
    const float*  wts = (const float*)d_in[1];
    float4*       o4  = (float4*)d_out;

    static cudaStream_t sR = nullptr, sA = nullptr;
    static cudaEvent_t  evStart = nullptr, evDone = nullptr;
    static cudaEvent_t  evRed[NCHUNK];
    if (sR == nullptr) {
        cudaStreamCreateWithFlags(&sR, cudaStreamNonBlocking);
        cudaStreamCreateWithFlags(&sA, cudaStreamNonBlocking);
        cudaEventCreateWithFlags(&evStart, cudaEventDisableTiming);
        cudaEventCreateWithFlags(&evDone, cudaEventDisableTiming);
        for (int i = 0; i < NCHUNK; i++)
            cudaEventCreateWithFlags(&evRed[i], cudaEventDisableTiming);
    }

    // fork from the harness stream
    cudaEventRecord(evStart, 0);
    cudaStreamWaitEvent(sR, evStart, 0);
    cudaStreamWaitEvent(sA, evStart, 0);

    for (int k = 0; k < NCHUNK; k++) {
        int b0 = k * CH_B;
        reduce_kernel<<<NRED_BLOCKS, 256, 0, sR>>>(x4, b0);
        cudaEventRecord(evRed[k], sR);
        cudaStreamWaitEvent(sA, evRed[k], 0);
        apply_kernel<<<NAPP_BLOCKS, 256, 0, sA>>>(x4, o4, wts, b0);
    }

    // join back to the harness stream (apply(last) transitively covers all)
    cudaEventRecord(evDone, sA);
    cudaStreamWaitEvent((cudaStream_t)0, evDone, 0);
}